// round 1
// baseline (speedup 1.0000x reference)
#include <cuda_runtime.h>
#include <cuda_bf16.h>

// Problem constants
#define BB 4
#define SS 2048
#define DD 768
#define HH 12
#define DH 64
#define MM (BB * SS)   // 8192 rows

// Scratch for Q, K, V projections, layout [B*S, D] (row-major, head-contiguous cols)
__device__ float g_q[MM * DD];
__device__ float g_k[MM * DD];
__device__ float g_v[MM * DD];

// ---------------------------------------------------------------------------
// GEMM: out[m][n] = sum_k X[m][k] * W[k][n] + bias[n]
// M=8192, N=768, K=768. 64x64 tiles, BK=16, 256 threads, 4x4 per thread.
// ---------------------------------------------------------------------------
__global__ __launch_bounds__(256) void gemm_qkv(
    const float* __restrict__ X,
    const float* __restrict__ W,
    const float* __restrict__ bias,
    float* __restrict__ out)
{
    __shared__ float Xs[64][16];
    __shared__ float Ws[16][64];

    const int tid = threadIdx.x;
    const int tx = tid & 15;
    const int ty = tid >> 4;
    const int n0 = blockIdx.x * 64;
    const int m0 = blockIdx.y * 64;

    const int xr  = tid >> 2;          // 0..63
    const int xc4 = (tid & 3) * 4;     // 0,4,8,12
    const int wr  = tid >> 4;          // 0..15
    const int wc4 = (tid & 15) * 4;    // 0..60

    float acc[4][4];
#pragma unroll
    for (int r = 0; r < 4; r++)
#pragma unroll
        for (int c = 0; c < 4; c++) acc[r][c] = 0.f;

    for (int k0 = 0; k0 < DD; k0 += 16) {
        float4 xv = *(const float4*)&X[(m0 + xr) * DD + k0 + xc4];
        float4 wv = *(const float4*)&W[(k0 + wr) * DD + n0 + wc4];
        __syncthreads();
        *(float4*)&Xs[xr][xc4] = xv;
        *(float4*)&Ws[wr][wc4] = wv;
        __syncthreads();
#pragma unroll
        for (int kk = 0; kk < 16; kk++) {
            float a0 = Xs[ty * 4 + 0][kk];
            float a1 = Xs[ty * 4 + 1][kk];
            float a2 = Xs[ty * 4 + 2][kk];
            float a3 = Xs[ty * 4 + 3][kk];
            float4 bv = *(float4*)&Ws[kk][tx * 4];
            acc[0][0] += a0 * bv.x; acc[0][1] += a0 * bv.y; acc[0][2] += a0 * bv.z; acc[0][3] += a0 * bv.w;
            acc[1][0] += a1 * bv.x; acc[1][1] += a1 * bv.y; acc[1][2] += a1 * bv.z; acc[1][3] += a1 * bv.w;
            acc[2][0] += a2 * bv.x; acc[2][1] += a2 * bv.y; acc[2][2] += a2 * bv.z; acc[2][3] += a2 * bv.w;
            acc[3][0] += a3 * bv.x; acc[3][1] += a3 * bv.y; acc[3][2] += a3 * bv.z; acc[3][3] += a3 * bv.w;
        }
    }

    float4 bb = *(const float4*)&bias[n0 + tx * 4];
#pragma unroll
    for (int r = 0; r < 4; r++) {
        float4 o;
        o.x = acc[r][0] + bb.x;
        o.y = acc[r][1] + bb.y;
        o.z = acc[r][2] + bb.z;
        o.w = acc[r][3] + bb.w;
        *(float4*)&out[(m0 + ty * 4 + r) * DD + n0 + tx * 4] = o;
    }
}

// ---------------------------------------------------------------------------
// Flash attention, causal. One block = one (b, h, 64-query tile).
// 256 threads: tx = key/dh dim (16), ty = query dim (16), 4x4 per thread.
// Shared tiles padded to stride 68 floats for conflict-free LDS.128.
// ---------------------------------------------------------------------------
#define SD 68

__global__ __launch_bounds__(256) void attn_kernel(
    const float* __restrict__ Q,
    const float* __restrict__ K,
    const float* __restrict__ V,
    float* __restrict__ out)
{
    extern __shared__ float sm[];
    float* Qs = sm;                 // [64][SD]
    float* Ks = sm + 64 * SD;       // [64][SD], reused as P tile
    float* Vs = sm + 2 * 64 * SD;   // [64][SD]

    const int tid = threadIdx.x;
    const int tx = tid & 15;
    const int ty = tid >> 4;
    const int bh = blockIdx.y;
    const int b = bh / HH;
    const int h = bh % HH;
    const int qt = (int)gridDim.x - 1 - (int)blockIdx.x;  // heavy tiles first
    const int q0 = qt * 64;
    const int rowbase = (b * SS) * DD + h * DH;  // base offset for this (b,h)

    // Load Q tile: 64 rows x 64 cols
#pragma unroll
    for (int i = 0; i < 4; i++) {
        int idx = i * 256 + tid;
        int r = idx >> 4;
        int c4 = (idx & 15) * 4;
        float4 qv = *(const float4*)&Q[rowbase + (q0 + r) * DD + c4];
        *(float4*)&Qs[r * SD + c4] = qv;
    }

    float m_i[4], l_i[4], acc[4][4];
#pragma unroll
    for (int r = 0; r < 4; r++) {
        m_i[r] = -1e30f;
        l_i[r] = 0.f;
#pragma unroll
        for (int c = 0; c < 4; c++) acc[r][c] = 0.f;
    }

    for (int kt = 0; kt <= qt; kt++) {
        const int k0 = kt * 64;
        __syncthreads();  // previous-iteration readers done (also orders Q stores)
#pragma unroll
        for (int i = 0; i < 4; i++) {
            int idx = i * 256 + tid;
            int r = idx >> 4;
            int c4 = (idx & 15) * 4;
            int g = rowbase + (k0 + r) * DD + c4;
            *(float4*)&Ks[r * SD + c4] = *(const float4*)&K[g];
            *(float4*)&Vs[r * SD + c4] = *(const float4*)&V[g];
        }
        __syncthreads();

        // Scores: s[r][c] = dot(Q row qi, K row kj), qi=ty*4+r, kj=tx*4+c
        float s[4][4];
#pragma unroll
        for (int r = 0; r < 4; r++)
#pragma unroll
            for (int c = 0; c < 4; c++) s[r][c] = 0.f;

#pragma unroll
        for (int d4 = 0; d4 < DH; d4 += 4) {
            float4 qv[4], kv[4];
#pragma unroll
            for (int r = 0; r < 4; r++)
                qv[r] = *(float4*)&Qs[(ty * 4 + r) * SD + d4];
#pragma unroll
            for (int c = 0; c < 4; c++)
                kv[c] = *(float4*)&Ks[(tx * 4 + c) * SD + d4];
#pragma unroll
            for (int r = 0; r < 4; r++)
#pragma unroll
                for (int c = 0; c < 4; c++) {
                    s[r][c] += qv[r].x * kv[c].x;
                    s[r][c] += qv[r].y * kv[c].y;
                    s[r][c] += qv[r].z * kv[c].z;
                    s[r][c] += qv[r].w * kv[c].w;
                }
        }

        // Scale + causal mask (diagonal tile only; kt<qt tiles fully valid)
        const bool diag = (kt == qt);
#pragma unroll
        for (int r = 0; r < 4; r++)
#pragma unroll
            for (int c = 0; c < 4; c++) {
                float v = s[r][c] * 0.125f;  // 1/sqrt(64)
                if (diag && (tx * 4 + c > ty * 4 + r)) v = -1e30f;
                s[r][c] = v;
            }

        // Online softmax update per owned query row
#pragma unroll
        for (int r = 0; r < 4; r++) {
            float mt = fmaxf(fmaxf(s[r][0], s[r][1]), fmaxf(s[r][2], s[r][3]));
#pragma unroll
            for (int o = 8; o > 0; o >>= 1)
                mt = fmaxf(mt, __shfl_xor_sync(0xffffffffu, mt, o, 16));
            float m_new = fmaxf(m_i[r], mt);
            float corr = __expf(m_i[r] - m_new);
            float p0 = __expf(s[r][0] - m_new);
            float p1 = __expf(s[r][1] - m_new);
            float p2 = __expf(s[r][2] - m_new);
            float p3 = __expf(s[r][3] - m_new);
            float psum = (p0 + p1) + (p2 + p3);
#pragma unroll
            for (int o = 8; o > 0; o >>= 1)
                psum += __shfl_xor_sync(0xffffffffu, psum, o, 16);
            l_i[r] = l_i[r] * corr + psum;
            m_i[r] = m_new;
            acc[r][0] *= corr; acc[r][1] *= corr; acc[r][2] *= corr; acc[r][3] *= corr;
            s[r][0] = p0; s[r][1] = p1; s[r][2] = p2; s[r][3] = p3;
        }

        __syncthreads();  // all threads done reading Ks
        // Write P tile into Ks buffer
#pragma unroll
        for (int r = 0; r < 4; r++) {
            float4 p4;
            p4.x = s[r][0]; p4.y = s[r][1]; p4.z = s[r][2]; p4.w = s[r][3];
            *(float4*)&Ks[(ty * 4 + r) * SD + tx * 4] = p4;
        }
        __syncthreads();

        // acc += P @ V
#pragma unroll 8
        for (int kj = 0; kj < 64; kj++) {
            float4 vv = *(float4*)&Vs[kj * SD + tx * 4];
#pragma unroll
            for (int r = 0; r < 4; r++) {
                float p = Ks[(ty * 4 + r) * SD + kj];
                acc[r][0] += p * vv.x;
                acc[r][1] += p * vv.y;
                acc[r][2] += p * vv.z;
                acc[r][3] += p * vv.w;
            }
        }
    }

    // Epilogue: normalize and store
#pragma unroll
    for (int r = 0; r < 4; r++) {
        float inv = 1.0f / l_i[r];
        float4 o;
        o.x = acc[r][0] * inv;
        o.y = acc[r][1] * inv;
        o.z = acc[r][2] * inv;
        o.w = acc[r][3] * inv;
        *(float4*)&out[rowbase + (q0 + ty * 4 + r) * DD + tx * 4] = o;
    }
}

// ---------------------------------------------------------------------------
extern "C" void kernel_launch(void* const* d_in, const int* in_sizes, int n_in,
                              void* d_out, int out_size)
{
    const float* X  = (const float*)d_in[0];
    // d_in[1] = attention_mask (unused by reference)
    const float* Wq = (const float*)d_in[2];
    const float* bq = (const float*)d_in[3];
    const float* Wk = (const float*)d_in[4];
    const float* bk = (const float*)d_in[5];
    const float* Wv = (const float*)d_in[6];
    const float* bv = (const float*)d_in[7];
    float* out = (float*)d_out;

    void *pq, *pk, *pv;
    cudaGetSymbolAddress(&pq, g_q);
    cudaGetSymbolAddress(&pk, g_k);
    cudaGetSymbolAddress(&pv, g_v);

    dim3 gg(DD / 64, MM / 64);  // (12, 128)
    gemm_qkv<<<gg, 256>>>(X, Wq, bq, (float*)pq);
    gemm_qkv<<<gg, 256>>>(X, Wk, bk, (float*)pk);
    gemm_qkv<<<gg, 256>>>(X, Wv, bv, (float*)pv);

    const int smem = 3 * 64 * SD * (int)sizeof(float);  // 52224 bytes
    cudaFuncSetAttribute(attn_kernel, cudaFuncAttributeMaxDynamicSharedMemorySize, smem);
    attn_kernel<<<dim3(SS / 64, BB * HH), 256, smem>>>(
        (const float*)pq, (const float*)pk, (const float*)pv, out);
}

// round 2
// speedup vs baseline: 1.8271x; 1.8271x over previous
#include <cuda_runtime.h>
#include <cuda_bf16.h>
#include <cstdint>

// Problem constants
#define BB 4
#define SS 2048
#define DD 768
#define HH 12
#define DH 64
#define MM (BB * SS)   // 8192 rows

// Scratch for Q, K, V projections, layout [B*S, D]
__device__ float g_q[MM * DD];
__device__ float g_k[MM * DD];
__device__ float g_v[MM * DD];

// ---------------------------------------------------------------------------
// GEMM: out = X @ W + bias   (unchanged from R1 — runs at fp32 FFMA peak)
// ---------------------------------------------------------------------------
__global__ __launch_bounds__(256) void gemm_qkv(
    const float* __restrict__ X,
    const float* __restrict__ W,
    const float* __restrict__ bias,
    float* __restrict__ out)
{
    __shared__ float Xs[64][16];
    __shared__ float Ws[16][64];

    const int tid = threadIdx.x;
    const int tx = tid & 15;
    const int ty = tid >> 4;
    const int n0 = blockIdx.x * 64;
    const int m0 = blockIdx.y * 64;

    const int xr  = tid >> 2;
    const int xc4 = (tid & 3) * 4;
    const int wr  = tid >> 4;
    const int wc4 = (tid & 15) * 4;

    float acc[4][4];
#pragma unroll
    for (int r = 0; r < 4; r++)
#pragma unroll
        for (int c = 0; c < 4; c++) acc[r][c] = 0.f;

    for (int k0 = 0; k0 < DD; k0 += 16) {
        float4 xv = *(const float4*)&X[(m0 + xr) * DD + k0 + xc4];
        float4 wv = *(const float4*)&W[(k0 + wr) * DD + n0 + wc4];
        __syncthreads();
        *(float4*)&Xs[xr][xc4] = xv;
        *(float4*)&Ws[wr][wc4] = wv;
        __syncthreads();
#pragma unroll
        for (int kk = 0; kk < 16; kk++) {
            float a0 = Xs[ty * 4 + 0][kk];
            float a1 = Xs[ty * 4 + 1][kk];
            float a2 = Xs[ty * 4 + 2][kk];
            float a3 = Xs[ty * 4 + 3][kk];
            float4 bv = *(float4*)&Ws[kk][tx * 4];
            acc[0][0] += a0 * bv.x; acc[0][1] += a0 * bv.y; acc[0][2] += a0 * bv.z; acc[0][3] += a0 * bv.w;
            acc[1][0] += a1 * bv.x; acc[1][1] += a1 * bv.y; acc[1][2] += a1 * bv.z; acc[1][3] += a1 * bv.w;
            acc[2][0] += a2 * bv.x; acc[2][1] += a2 * bv.y; acc[2][2] += a2 * bv.z; acc[2][3] += a2 * bv.w;
            acc[3][0] += a3 * bv.x; acc[3][1] += a3 * bv.y; acc[3][2] += a3 * bv.z; acc[3][3] += a3 * bv.w;
        }
    }

    float4 bb = *(const float4*)&bias[n0 + tx * 4];
#pragma unroll
    for (int r = 0; r < 4; r++) {
        float4 o;
        o.x = acc[r][0] + bb.x;
        o.y = acc[r][1] + bb.y;
        o.z = acc[r][2] + bb.z;
        o.w = acc[r][3] + bb.w;
        *(float4*)&out[(m0 + ty * 4 + r) * DD + n0 + tx * 4] = o;
    }
}

// ---------------------------------------------------------------------------
// Flash attention v2: tf32 mma.sync tensor cores.
// CTA: 256 threads = 8 warps. Q tile = 128 rows (16/warp), K tile = 64.
// Softmax fully warp-local. K/V in smem (stride 68 -> conflict-free frags).
// P round-trips through the recycled Q smem region (per-warp-private rows).
// ---------------------------------------------------------------------------
#define QT 128
#define KTL 64
#define SD 68   // SD % 32 == 4 -> fragment LDS banks = 4*g + qd (conflict-free)

__device__ __forceinline__ float to_tf32(float x) {
    unsigned r;
    asm("cvt.rna.tf32.f32 %0, %1;" : "=r"(r) : "f"(x));
    return __uint_as_float(r);
}

__device__ __forceinline__ void mma_tf32(float* c,
    float a0, float a1, float a2, float a3, float b0, float b1)
{
    asm volatile(
        "mma.sync.aligned.m16n8k8.row.col.f32.tf32.tf32.f32 "
        "{%0,%1,%2,%3},{%4,%5,%6,%7},{%8,%9},{%0,%1,%2,%3};"
        : "+f"(c[0]), "+f"(c[1]), "+f"(c[2]), "+f"(c[3])
        : "r"(__float_as_uint(a0)), "r"(__float_as_uint(a1)),
          "r"(__float_as_uint(a2)), "r"(__float_as_uint(a3)),
          "r"(__float_as_uint(b0)), "r"(__float_as_uint(b1)));
}

__global__ __launch_bounds__(256, 1) void attn_tc(
    const float* __restrict__ Q,
    const float* __restrict__ K,
    const float* __restrict__ V,
    float* __restrict__ out)
{
    extern __shared__ float smf[];
    float* Qs = smf;                 // [QT][SD]; recycled as P after frag build
    float* Ks = smf + QT * SD;       // [KTL][SD]
    float* Vs = Ks + KTL * SD;       // [KTL][SD]

    const int tid  = threadIdx.x;
    const int lane = tid & 31;
    const int w    = tid >> 5;       // warp 0..7
    const int g    = lane >> 2;      // 0..7 (row within fragment)
    const int qd   = lane & 3;       // 0..3 (quad column)
    const int bh   = blockIdx.y;
    const int b    = bh / HH;
    const int h    = bh % HH;
    const int qi   = (int)gridDim.x - 1 - (int)blockIdx.x;   // heavy first
    const int q0   = qi * QT;
    const int wrow = w * 16;
    const long rowbase = (long)(b * SS) * DD + h * DH;

    // ---- Load Q tile -> smem (tf32-rounded) ----
#pragma unroll
    for (int i = 0; i < (QT * DH) / (256 * 4); i++) {   // 8
        int idx = i * 256 + tid;
        int r = idx >> 4, c4 = (idx & 15) * 4;
        float4 v = *(const float4*)&Q[rowbase + (long)(q0 + r) * DD + c4];
        v.x = to_tf32(v.x); v.y = to_tf32(v.y);
        v.z = to_tf32(v.z); v.w = to_tf32(v.w);
        *(float4*)&Qs[r * SD + c4] = v;
    }
    __syncthreads();

    // ---- Q fragments held in registers for the whole key loop ----
    float qf[8][4];
#pragma unroll
    for (int k = 0; k < 8; k++) {
        qf[k][0] = Qs[(wrow + g)     * SD + k * 8 + qd];
        qf[k][1] = Qs[(wrow + g + 8) * SD + k * 8 + qd];
        qf[k][2] = Qs[(wrow + g)     * SD + k * 8 + qd + 4];
        qf[k][3] = Qs[(wrow + g + 8) * SD + k * 8 + qd + 4];
    }

    float o[8][4];
#pragma unroll
    for (int n = 0; n < 8; n++)
#pragma unroll
        for (int j = 0; j < 4; j++) o[n][j] = 0.f;
    float m0 = -1e30f, m1 = -1e30f, l0 = 0.f, l1 = 0.f;

    const int r0 = q0 + wrow + g;
    const int r1 = r0 + 8;
    const int nkt = 2 * qi + 2;

    for (int kt = 0; kt < nkt; kt++) {
        const int kb = kt * KTL;
        __syncthreads();   // previous-iteration K/V readers done
#pragma unroll
        for (int i = 0; i < (KTL * DH) / (256 * 4); i++) {  // 4
            int idx = i * 256 + tid;
            int r = idx >> 4, c4 = (idx & 15) * 4;
            long ga = rowbase + (long)(kb + r) * DD + c4;
            float4 kv = *(const float4*)&K[ga];
            float4 vv = *(const float4*)&V[ga];
            kv.x = to_tf32(kv.x); kv.y = to_tf32(kv.y);
            kv.z = to_tf32(kv.z); kv.w = to_tf32(kv.w);
            vv.x = to_tf32(vv.x); vv.y = to_tf32(vv.y);
            vv.z = to_tf32(vv.z); vv.w = to_tf32(vv.w);
            *(float4*)&Ks[r * SD + c4] = kv;
            *(float4*)&Vs[r * SD + c4] = vv;
        }
        __syncthreads();

        // ---- S = Q @ K^T : 8 k-steps x 8 n-tiles ----
        float s[8][4];
#pragma unroll
        for (int n = 0; n < 8; n++)
#pragma unroll
            for (int j = 0; j < 4; j++) s[n][j] = 0.f;

#pragma unroll
        for (int k = 0; k < 8; k++) {
#pragma unroll
            for (int n = 0; n < 8; n++) {
                float b0 = Ks[(n * 8 + g) * SD + k * 8 + qd];
                float b1 = Ks[(n * 8 + g) * SD + k * 8 + qd + 4];
                mma_tf32(s[n], qf[k][0], qf[k][1], qf[k][2], qf[k][3], b0, b1);
            }
        }

        // ---- scale + causal mask (diagonal tiles only) ----
        const bool dg = (kb + KTL - 1) > (q0 + wrow);
#pragma unroll
        for (int n = 0; n < 8; n++) {
            s[n][0] *= 0.125f; s[n][1] *= 0.125f;
            s[n][2] *= 0.125f; s[n][3] *= 0.125f;
            if (dg) {
                int c = kb + n * 8 + 2 * qd;
                if (c     > r0) s[n][0] = -1e30f;
                if (c + 1 > r0) s[n][1] = -1e30f;
                if (c     > r1) s[n][2] = -1e30f;
                if (c + 1 > r1) s[n][3] = -1e30f;
            }
        }

        // ---- warp-local online softmax (rows r0 and r1) ----
        float mx0 = -1e30f, mx1 = -1e30f;
#pragma unroll
        for (int n = 0; n < 8; n++) {
            mx0 = fmaxf(mx0, fmaxf(s[n][0], s[n][1]));
            mx1 = fmaxf(mx1, fmaxf(s[n][2], s[n][3]));
        }
        mx0 = fmaxf(mx0, __shfl_xor_sync(0xffffffffu, mx0, 1));
        mx0 = fmaxf(mx0, __shfl_xor_sync(0xffffffffu, mx0, 2));
        mx1 = fmaxf(mx1, __shfl_xor_sync(0xffffffffu, mx1, 1));
        mx1 = fmaxf(mx1, __shfl_xor_sync(0xffffffffu, mx1, 2));

        float mn0 = fmaxf(m0, mx0), mn1 = fmaxf(m1, mx1);
        float cr0 = __expf(m0 - mn0), cr1 = __expf(m1 - mn1);

        float sm0 = 0.f, sm1 = 0.f;
#pragma unroll
        for (int n = 0; n < 8; n++) {
            s[n][0] = __expf(s[n][0] - mn0);
            s[n][1] = __expf(s[n][1] - mn0);
            s[n][2] = __expf(s[n][2] - mn1);
            s[n][3] = __expf(s[n][3] - mn1);
            sm0 += s[n][0] + s[n][1];
            sm1 += s[n][2] + s[n][3];
        }
        sm0 += __shfl_xor_sync(0xffffffffu, sm0, 1);
        sm0 += __shfl_xor_sync(0xffffffffu, sm0, 2);
        sm1 += __shfl_xor_sync(0xffffffffu, sm1, 1);
        sm1 += __shfl_xor_sync(0xffffffffu, sm1, 2);

        l0 = l0 * cr0 + sm0;  l1 = l1 * cr1 + sm1;
        m0 = mn0;             m1 = mn1;
#pragma unroll
        for (int n = 0; n < 8; n++) {
            o[n][0] *= cr0; o[n][1] *= cr0;
            o[n][2] *= cr1; o[n][3] *= cr1;
        }

        // ---- P -> smem (recycled Q region; per-warp-private rows) ----
        float* Ps = Qs;
        __syncwarp();
#pragma unroll
        for (int n = 0; n < 8; n++) {
            float2 p01 = make_float2(to_tf32(s[n][0]), to_tf32(s[n][1]));
            float2 p23 = make_float2(to_tf32(s[n][2]), to_tf32(s[n][3]));
            *(float2*)&Ps[(wrow + g)     * SD + n * 8 + 2 * qd] = p01;
            *(float2*)&Ps[(wrow + g + 8) * SD + n * 8 + 2 * qd] = p23;
        }
        __syncwarp();

        // ---- O += P @ V ----
#pragma unroll
        for (int k = 0; k < 8; k++) {
            float a0 = Ps[(wrow + g)     * SD + k * 8 + qd];
            float a1 = Ps[(wrow + g + 8) * SD + k * 8 + qd];
            float a2 = Ps[(wrow + g)     * SD + k * 8 + qd + 4];
            float a3 = Ps[(wrow + g + 8) * SD + k * 8 + qd + 4];
#pragma unroll
            for (int n = 0; n < 8; n++) {
                float b0 = Vs[(k * 8 + qd)     * SD + n * 8 + g];
                float b1 = Vs[(k * 8 + qd + 4) * SD + n * 8 + g];
                mma_tf32(o[n], a0, a1, a2, a3, b0, b1);
            }
        }
    }

    // ---- epilogue: normalize, store ----
    float i0 = 1.f / l0, i1 = 1.f / l1;
#pragma unroll
    for (int n = 0; n < 8; n++) {
        float2 v0 = make_float2(o[n][0] * i0, o[n][1] * i0);
        float2 v1 = make_float2(o[n][2] * i1, o[n][3] * i1);
        *(float2*)&out[rowbase + (long)r0 * DD + n * 8 + 2 * qd] = v0;
        *(float2*)&out[rowbase + (long)r1 * DD + n * 8 + 2 * qd] = v1;
    }
}

// ---------------------------------------------------------------------------
extern "C" void kernel_launch(void* const* d_in, const int* in_sizes, int n_in,
                              void* d_out, int out_size)
{
    const float* X  = (const float*)d_in[0];
    // d_in[1] = attention_mask (unused by reference)
    const float* Wq = (const float*)d_in[2];
    const float* bq = (const float*)d_in[3];
    const float* Wk = (const float*)d_in[4];
    const float* bk = (const float*)d_in[5];
    const float* Wv = (const float*)d_in[6];
    const float* bv = (const float*)d_in[7];
    float* out = (float*)d_out;

    void *pq, *pk, *pv;
    cudaGetSymbolAddress(&pq, g_q);
    cudaGetSymbolAddress(&pk, g_k);
    cudaGetSymbolAddress(&pv, g_v);

    dim3 gg(DD / 64, MM / 64);
    gemm_qkv<<<gg, 256>>>(X, Wq, bq, (float*)pq);
    gemm_qkv<<<gg, 256>>>(X, Wk, bk, (float*)pk);
    gemm_qkv<<<gg, 256>>>(X, Wv, bv, (float*)pv);

    const int smem = (QT + 2 * KTL) * SD * (int)sizeof(float);  // 69632 B
    cudaFuncSetAttribute(attn_tc, cudaFuncAttributeMaxDynamicSharedMemorySize, smem);
    attn_tc<<<dim3(SS / QT, BB * HH), 256, smem>>>(
        (const float*)pq, (const float*)pk, (const float*)pv, out);
}

// round 3
// speedup vs baseline: 3.6491x; 1.9972x over previous
#include <cuda_runtime.h>
#include <cuda_bf16.h>
#include <cstdint>

// Problem constants
#define BB 4
#define SS 2048
#define DD 768
#define HH 12
#define DH 64
#define MM (BB * SS)   // 8192 rows

// Scratch for Q, K, V projections, layout [B*S, D]
__device__ float g_q[MM * DD];
__device__ float g_k[MM * DD];
__device__ float g_v[MM * DD];

__device__ __forceinline__ float to_tf32(float x) {
    unsigned r;
    asm("cvt.rna.tf32.f32 %0, %1;" : "=r"(r) : "f"(x));
    return __uint_as_float(r);
}

__device__ __forceinline__ void mma_tf32(float* c,
    float a0, float a1, float a2, float a3, float b0, float b1)
{
    asm volatile(
        "mma.sync.aligned.m16n8k8.row.col.f32.tf32.tf32.f32 "
        "{%0,%1,%2,%3},{%4,%5,%6,%7},{%8,%9},{%0,%1,%2,%3};"
        : "+f"(c[0]), "+f"(c[1]), "+f"(c[2]), "+f"(c[3])
        : "r"(__float_as_uint(a0)), "r"(__float_as_uint(a1)),
          "r"(__float_as_uint(a2)), "r"(__float_as_uint(a3)),
          "r"(__float_as_uint(b0)), "r"(__float_as_uint(b1)));
}

// ---------------------------------------------------------------------------
// Fused QKV projection GEMM on tf32 tensor cores.
// out_z = X @ W_z + b_z for z in {q,k,v} (blockIdx.z).
// CTA tile 128x128, BK=32, 256 threads (8 warps, 2x4), warp tile 64x32.
// Single-sync register double buffering.
// As stride 36, Bs stride 132 (both == 4 mod 32 -> conflict-free frag LDS).
// ---------------------------------------------------------------------------
#define GAS 36    // As row stride (floats)
#define GBS 132   // Bs row stride (floats)
#define ASZ (128 * GAS)   // 4608
#define BSZ (32 * GBS)    // 4224

__global__ __launch_bounds__(256) void gemm_tc(
    const float* __restrict__ X,
    const float* __restrict__ Wq, const float* __restrict__ bq,
    const float* __restrict__ Wk, const float* __restrict__ bk,
    const float* __restrict__ Wv, const float* __restrict__ bv,
    float* __restrict__ oq, float* __restrict__ okk, float* __restrict__ ov)
{
    const int z = blockIdx.z;
    const float* W    = (z == 0) ? Wq : (z == 1) ? Wk : Wv;
    const float* bias = (z == 0) ? bq : (z == 1) ? bk : bv;
    float* out        = (z == 0) ? oq : (z == 1) ? okk : ov;

    extern __shared__ float sm[];
    float* As = sm;               // [2][128][GAS]
    float* Bs = sm + 2 * ASZ;     // [2][32][GBS]

    const int tid  = threadIdx.x;
    const int lane = tid & 31;
    const int w    = tid >> 5;
    const int g    = lane >> 2;
    const int qd   = lane & 3;
    const int wm   = w >> 2;          // 0..1
    const int wn   = w & 3;           // 0..3
    const int m0   = blockIdx.y * 128;
    const int n0   = blockIdx.x * 128;

    const int lr  = tid >> 3;         // 0..31
    const int lc4 = (tid & 7) * 4;    // 0..28

    float4 ar[4], br[4];
    float acc[4][4][4];
#pragma unroll
    for (int mf = 0; mf < 4; mf++)
#pragma unroll
        for (int nf = 0; nf < 4; nf++)
#pragma unroll
            for (int j = 0; j < 4; j++) acc[mf][nf][j] = 0.f;

#define LDG_TILE(t)                                                         \
    {                                                                       \
        const int k0 = (t) * 32;                                            \
        _Pragma("unroll")                                                   \
        for (int j = 0; j < 4; j++)                                         \
            ar[j] = *(const float4*)&X[(long)(m0 + lr + 32 * j) * DD + k0 + lc4]; \
        _Pragma("unroll")                                                   \
        for (int j = 0; j < 4; j++)                                         \
            br[j] = *(const float4*)&W[(long)(k0 + lr) * DD + n0 + lc4 + 32 * j]; \
    }

#define STS_TILE(bsel)                                                      \
    {                                                                       \
        float* A = As + (bsel) * ASZ;                                       \
        float* B = Bs + 2 * ASZ - 2 * ASZ + (bsel) * BSZ + 2 * ASZ;         \
        B = sm + 2 * ASZ + (bsel) * BSZ;                                    \
        _Pragma("unroll")                                                   \
        for (int j = 0; j < 4; j++) {                                       \
            float4 v = ar[j];                                               \
            v.x = to_tf32(v.x); v.y = to_tf32(v.y);                         \
            v.z = to_tf32(v.z); v.w = to_tf32(v.w);                         \
            *(float4*)&A[(lr + 32 * j) * GAS + lc4] = v;                    \
        }                                                                   \
        _Pragma("unroll")                                                   \
        for (int j = 0; j < 4; j++) {                                       \
            float4 v = br[j];                                               \
            v.x = to_tf32(v.x); v.y = to_tf32(v.y);                         \
            v.z = to_tf32(v.z); v.w = to_tf32(v.w);                         \
            *(float4*)&B[lr * GBS + lc4 + 32 * j] = v;                      \
        }                                                                   \
    }

#define COMPUTE(bsel)                                                       \
    {                                                                       \
        const float* A = As + (bsel) * ASZ + (wm * 64) * GAS;               \
        const float* B = sm + 2 * ASZ + (bsel) * BSZ + wn * 32;             \
        _Pragma("unroll")                                                   \
        for (int ks = 0; ks < 4; ks++) {                                    \
            float a[4][4];                                                  \
            _Pragma("unroll")                                               \
            for (int mf = 0; mf < 4; mf++) {                                \
                a[mf][0] = A[(mf * 16 + g)     * GAS + ks * 8 + qd];        \
                a[mf][1] = A[(mf * 16 + g + 8) * GAS + ks * 8 + qd];        \
                a[mf][2] = A[(mf * 16 + g)     * GAS + ks * 8 + qd + 4];    \
                a[mf][3] = A[(mf * 16 + g + 8) * GAS + ks * 8 + qd + 4];    \
            }                                                               \
            float bf[4][2];                                                 \
            _Pragma("unroll")                                               \
            for (int nf = 0; nf < 4; nf++) {                                \
                bf[nf][0] = B[(ks * 8 + qd)     * GBS + nf * 8 + g];        \
                bf[nf][1] = B[(ks * 8 + qd + 4) * GBS + nf * 8 + g];        \
            }                                                               \
            _Pragma("unroll")                                               \
            for (int mf = 0; mf < 4; mf++)                                  \
                _Pragma("unroll")                                           \
                for (int nf = 0; nf < 4; nf++)                              \
                    mma_tf32(acc[mf][nf], a[mf][0], a[mf][1], a[mf][2],     \
                             a[mf][3], bf[nf][0], bf[nf][1]);               \
        }                                                                   \
    }

    const int T = DD / 32;   // 24

    LDG_TILE(0);
    STS_TILE(0);
    __syncthreads();
    LDG_TILE(1);

    int buf = 0;
#pragma unroll 1
    for (int t = 0; t < T; t++) {
        if (t + 1 < T) STS_TILE(buf ^ 1);
        if (t + 2 < T) LDG_TILE(t + 2);
        COMPUTE(buf);
        __syncthreads();
        buf ^= 1;
    }

    // Epilogue: add bias, store fp32
#pragma unroll
    for (int mf = 0; mf < 4; mf++) {
        const int row0 = m0 + wm * 64 + mf * 16 + g;
#pragma unroll
        for (int nf = 0; nf < 4; nf++) {
            const int col = n0 + wn * 32 + nf * 8 + 2 * qd;
            const float bx = __ldg(&bias[col]);
            const float by = __ldg(&bias[col + 1]);
            float2 v0 = make_float2(acc[mf][nf][0] + bx, acc[mf][nf][1] + by);
            float2 v1 = make_float2(acc[mf][nf][2] + bx, acc[mf][nf][3] + by);
            *(float2*)&out[(long)row0 * DD + col] = v0;
            *(float2*)&out[(long)(row0 + 8) * DD + col] = v1;
        }
    }
}

// ---------------------------------------------------------------------------
// Flash attention: tf32 mma.sync tensor cores (unchanged from R2).
// ---------------------------------------------------------------------------
#define QT 128
#define KTL 64
#define SD 68

__global__ __launch_bounds__(256, 1) void attn_tc(
    const float* __restrict__ Q,
    const float* __restrict__ K,
    const float* __restrict__ V,
    float* __restrict__ out)
{
    extern __shared__ float smf[];
    float* Qs = smf;
    float* Ks = smf + QT * SD;
    float* Vs = Ks + KTL * SD;

    const int tid  = threadIdx.x;
    const int lane = tid & 31;
    const int w    = tid >> 5;
    const int g    = lane >> 2;
    const int qd   = lane & 3;
    const int bh   = blockIdx.y;
    const int b    = bh / HH;
    const int h    = bh % HH;
    const int qi   = (int)gridDim.x - 1 - (int)blockIdx.x;
    const int q0   = qi * QT;
    const int wrow = w * 16;
    const long rowbase = (long)(b * SS) * DD + h * DH;

#pragma unroll
    for (int i = 0; i < (QT * DH) / (256 * 4); i++) {
        int idx = i * 256 + tid;
        int r = idx >> 4, c4 = (idx & 15) * 4;
        float4 v = *(const float4*)&Q[rowbase + (long)(q0 + r) * DD + c4];
        v.x = to_tf32(v.x); v.y = to_tf32(v.y);
        v.z = to_tf32(v.z); v.w = to_tf32(v.w);
        *(float4*)&Qs[r * SD + c4] = v;
    }
    __syncthreads();

    float qf[8][4];
#pragma unroll
    for (int k = 0; k < 8; k++) {
        qf[k][0] = Qs[(wrow + g)     * SD + k * 8 + qd];
        qf[k][1] = Qs[(wrow + g + 8) * SD + k * 8 + qd];
        qf[k][2] = Qs[(wrow + g)     * SD + k * 8 + qd + 4];
        qf[k][3] = Qs[(wrow + g + 8) * SD + k * 8 + qd + 4];
    }

    float o[8][4];
#pragma unroll
    for (int n = 0; n < 8; n++)
#pragma unroll
        for (int j = 0; j < 4; j++) o[n][j] = 0.f;
    float m0 = -1e30f, m1 = -1e30f, l0 = 0.f, l1 = 0.f;

    const int r0 = q0 + wrow + g;
    const int r1 = r0 + 8;
    const int nkt = 2 * qi + 2;

    for (int kt = 0; kt < nkt; kt++) {
        const int kb = kt * KTL;
        __syncthreads();
#pragma unroll
        for (int i = 0; i < (KTL * DH) / (256 * 4); i++) {
            int idx = i * 256 + tid;
            int r = idx >> 4, c4 = (idx & 15) * 4;
            long ga = rowbase + (long)(kb + r) * DD + c4;
            float4 kv = *(const float4*)&K[ga];
            float4 vv = *(const float4*)&V[ga];
            kv.x = to_tf32(kv.x); kv.y = to_tf32(kv.y);
            kv.z = to_tf32(kv.z); kv.w = to_tf32(kv.w);
            vv.x = to_tf32(vv.x); vv.y = to_tf32(vv.y);
            vv.z = to_tf32(vv.z); vv.w = to_tf32(vv.w);
            *(float4*)&Ks[r * SD + c4] = kv;
            *(float4*)&Vs[r * SD + c4] = vv;
        }
        __syncthreads();

        float s[8][4];
#pragma unroll
        for (int n = 0; n < 8; n++)
#pragma unroll
            for (int j = 0; j < 4; j++) s[n][j] = 0.f;

#pragma unroll
        for (int k = 0; k < 8; k++) {
#pragma unroll
            for (int n = 0; n < 8; n++) {
                float b0 = Ks[(n * 8 + g) * SD + k * 8 + qd];
                float b1 = Ks[(n * 8 + g) * SD + k * 8 + qd + 4];
                mma_tf32(s[n], qf[k][0], qf[k][1], qf[k][2], qf[k][3], b0, b1);
            }
        }

        const bool dg = (kb + KTL - 1) > (q0 + wrow);
#pragma unroll
        for (int n = 0; n < 8; n++) {
            s[n][0] *= 0.125f; s[n][1] *= 0.125f;
            s[n][2] *= 0.125f; s[n][3] *= 0.125f;
            if (dg) {
                int c = kb + n * 8 + 2 * qd;
                if (c     > r0) s[n][0] = -1e30f;
                if (c + 1 > r0) s[n][1] = -1e30f;
                if (c     > r1) s[n][2] = -1e30f;
                if (c + 1 > r1) s[n][3] = -1e30f;
            }
        }

        float mx0 = -1e30f, mx1 = -1e30f;
#pragma unroll
        for (int n = 0; n < 8; n++) {
            mx0 = fmaxf(mx0, fmaxf(s[n][0], s[n][1]));
            mx1 = fmaxf(mx1, fmaxf(s[n][2], s[n][3]));
        }
        mx0 = fmaxf(mx0, __shfl_xor_sync(0xffffffffu, mx0, 1));
        mx0 = fmaxf(mx0, __shfl_xor_sync(0xffffffffu, mx0, 2));
        mx1 = fmaxf(mx1, __shfl_xor_sync(0xffffffffu, mx1, 1));
        mx1 = fmaxf(mx1, __shfl_xor_sync(0xffffffffu, mx1, 2));

        float mn0 = fmaxf(m0, mx0), mn1 = fmaxf(m1, mx1);
        float cr0 = __expf(m0 - mn0), cr1 = __expf(m1 - mn1);

        float sm0 = 0.f, sm1 = 0.f;
#pragma unroll
        for (int n = 0; n < 8; n++) {
            s[n][0] = __expf(s[n][0] - mn0);
            s[n][1] = __expf(s[n][1] - mn0);
            s[n][2] = __expf(s[n][2] - mn1);
            s[n][3] = __expf(s[n][3] - mn1);
            sm0 += s[n][0] + s[n][1];
            sm1 += s[n][2] + s[n][3];
        }
        sm0 += __shfl_xor_sync(0xffffffffu, sm0, 1);
        sm0 += __shfl_xor_sync(0xffffffffu, sm0, 2);
        sm1 += __shfl_xor_sync(0xffffffffu, sm1, 1);
        sm1 += __shfl_xor_sync(0xffffffffu, sm1, 2);

        l0 = l0 * cr0 + sm0;  l1 = l1 * cr1 + sm1;
        m0 = mn0;             m1 = mn1;
#pragma unroll
        for (int n = 0; n < 8; n++) {
            o[n][0] *= cr0; o[n][1] *= cr0;
            o[n][2] *= cr1; o[n][3] *= cr1;
        }

        float* Ps = Qs;
        __syncwarp();
#pragma unroll
        for (int n = 0; n < 8; n++) {
            float2 p01 = make_float2(to_tf32(s[n][0]), to_tf32(s[n][1]));
            float2 p23 = make_float2(to_tf32(s[n][2]), to_tf32(s[n][3]));
            *(float2*)&Ps[(wrow + g)     * SD + n * 8 + 2 * qd] = p01;
            *(float2*)&Ps[(wrow + g + 8) * SD + n * 8 + 2 * qd] = p23;
        }
        __syncwarp();

#pragma unroll
        for (int k = 0; k < 8; k++) {
            float a0 = Ps[(wrow + g)     * SD + k * 8 + qd];
            float a1 = Ps[(wrow + g + 8) * SD + k * 8 + qd];
            float a2 = Ps[(wrow + g)     * SD + k * 8 + qd + 4];
            float a3 = Ps[(wrow + g + 8) * SD + k * 8 + qd + 4];
#pragma unroll
            for (int n = 0; n < 8; n++) {
                float b0 = Vs[(k * 8 + qd)     * SD + n * 8 + g];
                float b1 = Vs[(k * 8 + qd + 4) * SD + n * 8 + g];
                mma_tf32(o[n], a0, a1, a2, a3, b0, b1);
            }
        }
    }

    float i0 = 1.f / l0, i1 = 1.f / l1;
#pragma unroll
    for (int n = 0; n < 8; n++) {
        float2 v0 = make_float2(o[n][0] * i0, o[n][1] * i0);
        float2 v1 = make_float2(o[n][2] * i1, o[n][3] * i1);
        *(float2*)&out[rowbase + (long)r0 * DD + n * 8 + 2 * qd] = v0;
        *(float2*)&out[rowbase + (long)r1 * DD + n * 8 + 2 * qd] = v1;
    }
}

// ---------------------------------------------------------------------------
extern "C" void kernel_launch(void* const* d_in, const int* in_sizes, int n_in,
                              void* d_out, int out_size)
{
    const float* X  = (const float*)d_in[0];
    // d_in[1] = attention_mask (unused by reference)
    const float* Wq = (const float*)d_in[2];
    const float* bq = (const float*)d_in[3];
    const float* Wk = (const float*)d_in[4];
    const float* bk = (const float*)d_in[5];
    const float* Wv = (const float*)d_in[6];
    const float* bv = (const float*)d_in[7];
    float* out = (float*)d_out;

    void *pq, *pk, *pv;
    cudaGetSymbolAddress(&pq, g_q);
    cudaGetSymbolAddress(&pk, g_k);
    cudaGetSymbolAddress(&pv, g_v);

    const int gsmem = (2 * ASZ + 2 * BSZ) * (int)sizeof(float);  // 70656 B
    cudaFuncSetAttribute(gemm_tc, cudaFuncAttributeMaxDynamicSharedMemorySize, gsmem);
    gemm_tc<<<dim3(DD / 128, MM / 128, 3), 256, gsmem>>>(
        X, Wq, bq, Wk, bk, Wv, bv, (float*)pq, (float*)pk, (float*)pv);

    const int asmem = (QT + 2 * KTL) * SD * (int)sizeof(float);  // 69632 B
    cudaFuncSetAttribute(attn_tc, cudaFuncAttributeMaxDynamicSharedMemorySize, asmem);
    attn_tc<<<dim3(SS / QT, BB * HH), 256, asmem>>>(
        (const float*)pq, (const float*)pk, (const float*)pv, out);
}